// round 1
// baseline (speedup 1.0000x reference)
#include <cuda_runtime.h>
#include <mma.h>

using namespace nvcuda;

// Problem constants (fixed by the dataset)
#define DIN   1024
#define DOUT  1024
#define BB    2
#define SEQ   2048
#define NH    16
#define HDIM  64
#define MROWS (BB * SEQ)            // 4096
#define QKVLD (3 * DOUT)            // 3072

#define INV_SCALE 0.17677669529663687f   // 1 / 1024^0.25

// Scratch (allocation-free: __device__ globals)
__device__ float g_qkv[(size_t)MROWS * QKVLD];  // [4096][3072]  q|k|v per row
__device__ float g_ctx[(size_t)MROWS * DOUT];   // [4096][1024]

__device__ __forceinline__ float to_tf32(float x) { return wmma::__float_to_tf32(x); }

// ---------------------------------------------------------------------------
// Generic GEMM: C[m, coff+n] = sum_k A[m,k] * W[n,k]  (+ bias[n])
// A: [M, K] row-major, W: [N, K] row-major (i.e. C = A @ W^T), C ld = ldc.
// Block tile 64x64, BK=32, 128 threads (4 warps, each 32x32 via 2x2 wmma).
// M, N assumed multiples of 64; K multiple of 32 (true for all calls here).
// ---------------------------------------------------------------------------
__global__ void __launch_bounds__(128)
gemm_xwT_kernel(const float* __restrict__ A, const float* __restrict__ W,
                const float* __restrict__ bias, float* __restrict__ C,
                int K, int ldc, int coff)
{
    __shared__ float sm[5120];           // As[64][40] + Bs[64][40]; reused as Cs[64][68]
    float* As = sm;                      // 2560 floats
    float* Bs = sm + 2560;               // 2560 floats

    const int m0 = blockIdx.y * 64;
    const int n0 = blockIdx.x * 64;
    const int tid  = threadIdx.x;
    const int warp = tid >> 5;
    const int wm = (warp >> 1) * 32;     // warp row offset within tile
    const int wn = (warp & 1) * 32;      // warp col offset within tile

    wmma::fragment<wmma::accumulator, 16, 16, 8, float> acc[2][2];
#pragma unroll
    for (int i = 0; i < 2; i++)
#pragma unroll
        for (int j = 0; j < 2; j++)
            wmma::fill_fragment(acc[i][j], 0.0f);

    for (int k0 = 0; k0 < K; k0 += 32) {
#pragma unroll
        for (int i = tid; i < 512; i += 128) {
            int r = i >> 3, c = (i & 7) * 4;
            *(float4*)&As[r * 40 + c] = *(const float4*)&A[(size_t)(m0 + r) * K + k0 + c];
            *(float4*)&Bs[r * 40 + c] = *(const float4*)&W[(size_t)(n0 + r) * K + k0 + c];
        }
        __syncthreads();

#pragma unroll
        for (int kk = 0; kk < 32; kk += 8) {
            wmma::fragment<wmma::matrix_a, 16, 16, 8, wmma::precision::tf32, wmma::row_major> af[2];
            wmma::fragment<wmma::matrix_b, 16, 16, 8, wmma::precision::tf32, wmma::col_major> bf[2];
#pragma unroll
            for (int i = 0; i < 2; i++) {
                wmma::load_matrix_sync(af[i], As + (wm + 16 * i) * 40 + kk, 40);
#pragma unroll
                for (int e = 0; e < af[i].num_elements; e++) af[i].x[e] = to_tf32(af[i].x[e]);
            }
#pragma unroll
            for (int j = 0; j < 2; j++) {
                wmma::load_matrix_sync(bf[j], Bs + (wn + 16 * j) * 40 + kk, 40);
#pragma unroll
                for (int e = 0; e < bf[j].num_elements; e++) bf[j].x[e] = to_tf32(bf[j].x[e]);
            }
#pragma unroll
            for (int i = 0; i < 2; i++)
#pragma unroll
                for (int j = 0; j < 2; j++)
                    wmma::mma_sync(acc[i][j], af[i], bf[j], acc[i][j]);
        }
        __syncthreads();
    }

    // Epilogue: stage to smem (Cs[64][68]), add bias, coalesced store.
    float* Cs = sm;
#pragma unroll
    for (int i = 0; i < 2; i++)
#pragma unroll
        for (int j = 0; j < 2; j++)
            wmma::store_matrix_sync(Cs + (wm + 16 * i) * 68 + wn + 16 * j,
                                    acc[i][j], 68, wmma::mem_row_major);
    __syncthreads();
#pragma unroll
    for (int i = tid; i < 1024; i += 128) {
        int r = i >> 4, c = (i & 15) * 4;
        float4 v = *(float4*)&Cs[r * 68 + c];
        if (bias) {
            v.x += bias[n0 + c];
            v.y += bias[n0 + c + 1];
            v.z += bias[n0 + c + 2];
            v.w += bias[n0 + c + 3];
        }
        *(float4*)&C[(size_t)(m0 + r) * ldc + coff + n0 + c] = v;
    }
}

// ---------------------------------------------------------------------------
// Flash attention (causal), per (b,h), 64-query tiles, 64-key tiles, head=64.
// Q kept in registers as tf32 A-fragments; K/V staged in smem; online softmax
// in fp32; accumulator rescale done via an identical accumulator fragment
// loaded from a row-broadcast alpha tile (layout-agnostic elementwise mul).
// ---------------------------------------------------------------------------
#define ILD 68
#define ATTN_SMEM ((3 * 64 * ILD + 1024 + 192) * 4)   // 57088 bytes

__global__ void __launch_bounds__(128)
attn_kernel(const float* __restrict__ qkv, float* __restrict__ ctx)
{
    extern __shared__ float sm[];
    float* Ks   = sm;                    // [64][68]
    float* Vs   = sm + 64 * ILD;         // [64][68]
    float* Ss   = sm + 2 * 64 * ILD;     // [64][68]  scores / P / staging
    float* AF   = sm + 3 * 64 * ILD;     // [64][16]  row-broadcast alpha
    float* rowm = AF + 1024;             // [64]
    float* rowl = rowm + 64;             // [64]
    float* rowa = rowl + 64;             // [64]

    const int qt = blockIdx.x;
    const int bh = blockIdx.y;
    const int b  = bh >> 4;
    const int h  = bh & 15;
    const int q0 = qt * 64;
    const int tid  = threadIdx.x;
    const int warp = tid >> 5;

    const float* qbase = qkv + (size_t)b * SEQ * QKVLD + h * HDIM;
    const float* kbase = qbase + DOUT;
    const float* vbase = qbase + 2 * DOUT;

    // Stage Q tile, preload A-fragments (8 k-steps of 8), then free Ss.
#pragma unroll
    for (int i = tid; i < 1024; i += 128) {
        int r = i >> 4, c = (i & 15) * 4;
        *(float4*)&Ss[r * ILD + c] = *(const float4*)&qbase[(size_t)(q0 + r) * QKVLD + c];
    }
    __syncthreads();
    wmma::fragment<wmma::matrix_a, 16, 16, 8, wmma::precision::tf32, wmma::row_major> qf[8];
#pragma unroll
    for (int s = 0; s < 8; s++) {
        wmma::load_matrix_sync(qf[s], Ss + warp * 16 * ILD + s * 8, ILD);
#pragma unroll
        for (int e = 0; e < qf[s].num_elements; e++) qf[s].x[e] = to_tf32(qf[s].x[e]);
    }
    __syncthreads();

    wmma::fragment<wmma::accumulator, 16, 16, 8, float> of[4];
#pragma unroll
    for (int j = 0; j < 4; j++) wmma::fill_fragment(of[j], 0.0f);

    if (tid < 64) { rowm[tid] = -1e30f; rowl[tid] = 0.0f; }
    __syncthreads();

    const int nkv = q0 + 64;             // exclusive key bound (causal)
    for (int j0 = 0; j0 < nkv; j0 += 64) {
        // Stage K and V tiles (coalesced float4)
#pragma unroll
        for (int i = tid; i < 1024; i += 128) {
            int r = i >> 4, c = (i & 15) * 4;
            *(float4*)&Ks[r * ILD + c] = *(const float4*)&kbase[(size_t)(j0 + r) * QKVLD + c];
            *(float4*)&Vs[r * ILD + c] = *(const float4*)&vbase[(size_t)(j0 + r) * QKVLD + c];
        }
        __syncthreads();

        // S = Q K^T  (each warp: 16 rows x 64 cols)
        wmma::fragment<wmma::accumulator, 16, 16, 8, float> sf[4];
#pragma unroll
        for (int j = 0; j < 4; j++) wmma::fill_fragment(sf[j], 0.0f);
#pragma unroll
        for (int s = 0; s < 8; s++) {
#pragma unroll
            for (int j = 0; j < 4; j++) {
                wmma::fragment<wmma::matrix_b, 16, 16, 8, wmma::precision::tf32, wmma::col_major> bf;
                wmma::load_matrix_sync(bf, Ks + (j * 16) * ILD + s * 8, ILD);
#pragma unroll
                for (int e = 0; e < bf.num_elements; e++) bf.x[e] = to_tf32(bf.x[e]);
                wmma::mma_sync(sf[j], qf[s], bf, sf[j]);
            }
        }
#pragma unroll
        for (int j = 0; j < 4; j++)
            wmma::store_matrix_sync(Ss + warp * 16 * ILD + j * 16, sf[j], ILD, wmma::mem_row_major);
        __syncthreads();

        // Online softmax: thread pair (t, t^1) owns one row (32 cols each)
        {
            const int r  = tid >> 1;
            const int c0 = (tid & 1) * 32;
            const int qg = q0 + r;
            float mx = -1e30f;
#pragma unroll
            for (int c = 0; c < 32; c++) {
                int kg = j0 + c0 + c;
                if (kg <= qg) mx = fmaxf(mx, Ss[r * ILD + c0 + c] * INV_SCALE);
            }
            mx = fmaxf(mx, __shfl_xor_sync(0xffffffffu, mx, 1));
            const float mo = rowm[r];
            const float mn = fmaxf(mo, mx);
            float lsum = 0.0f;
#pragma unroll
            for (int c = 0; c < 32; c++) {
                int kg = j0 + c0 + c;
                float p = 0.0f;
                if (kg <= qg) p = __expf(Ss[r * ILD + c0 + c] * INV_SCALE - mn);
                Ss[r * ILD + c0 + c] = p;
                lsum += p;
            }
            lsum += __shfl_xor_sync(0xffffffffu, lsum, 1);
            if ((tid & 1) == 0) {
                rowm[r] = mn;
                rowl[r] = rowl[r] * __expf(mo - mn) + lsum;
                rowa[r] = __expf(mo - mn);
            }
        }
        __syncthreads();

        // Broadcast alpha per row into AF[64][16]
#pragma unroll
        for (int i = tid; i < 1024; i += 128) AF[i] = rowa[i >> 4];
        __syncthreads();

        // Rescale O accumulators (layout-agnostic: identical frag types)
        {
            wmma::fragment<wmma::accumulator, 16, 16, 8, float> af;
            wmma::load_matrix_sync(af, AF + warp * 16 * 16, 16, wmma::mem_row_major);
#pragma unroll
            for (int j = 0; j < 4; j++)
#pragma unroll
                for (int e = 0; e < af.num_elements; e++) of[j].x[e] *= af.x[e];
        }

        // O += P V
#pragma unroll
        for (int s = 0; s < 8; s++) {
            wmma::fragment<wmma::matrix_a, 16, 16, 8, wmma::precision::tf32, wmma::row_major> pf;
            wmma::load_matrix_sync(pf, Ss + warp * 16 * ILD + s * 8, ILD);
#pragma unroll
            for (int e = 0; e < pf.num_elements; e++) pf.x[e] = to_tf32(pf.x[e]);
#pragma unroll
            for (int j = 0; j < 4; j++) {
                wmma::fragment<wmma::matrix_b, 16, 16, 8, wmma::precision::tf32, wmma::row_major> vf;
                wmma::load_matrix_sync(vf, Vs + (s * 8) * ILD + j * 16, ILD);
#pragma unroll
                for (int e = 0; e < vf.num_elements; e++) vf.x[e] = to_tf32(vf.x[e]);
                wmma::mma_sync(of[j], pf, vf, of[j]);
            }
        }
        __syncthreads();   // protect Ks/Vs/Ss/AF before next iteration
    }

    // Epilogue: O -> smem, divide by l, store ctx in [b, s, h*64+d] layout
#pragma unroll
    for (int j = 0; j < 4; j++)
        wmma::store_matrix_sync(Ss + warp * 16 * ILD + j * 16, of[j], ILD, wmma::mem_row_major);
    __syncthreads();
#pragma unroll
    for (int i = tid; i < 1024; i += 128) {
        int r = i >> 4, c = (i & 15) * 4;
        float inv = 1.0f / rowl[r];
        float4 v = *(float4*)&Ss[r * ILD + c];
        v.x *= inv; v.y *= inv; v.z *= inv; v.w *= inv;
        *(float4*)&ctx[((size_t)b * SEQ + q0 + r) * DOUT + h * HDIM + c] = v;
    }
}

// ---------------------------------------------------------------------------
extern "C" void kernel_launch(void* const* d_in, const int* in_sizes, int n_in,
                              void* d_out, int out_size)
{
    (void)in_sizes; (void)n_in; (void)out_size;
    const float* x  = (const float*)d_in[0];
    const float* Wq = (const float*)d_in[1];
    const float* Wk = (const float*)d_in[2];
    const float* Wv = (const float*)d_in[3];
    const float* Wo = (const float*)d_in[4];
    const float* bo = (const float*)d_in[5];
    float* out = (float*)d_out;

    float *qkv = nullptr, *ctx = nullptr;
    cudaGetSymbolAddress((void**)&qkv, g_qkv);
    cudaGetSymbolAddress((void**)&ctx, g_ctx);

    cudaFuncSetAttribute(attn_kernel, cudaFuncAttributeMaxDynamicSharedMemorySize, ATTN_SMEM);

    dim3 blk(128);
    dim3 gp(DOUT / 64, MROWS / 64);      // (16, 64)

    // QKV projections into fused scratch [4096][3072]
    gemm_xwT_kernel<<<gp, blk>>>(x, Wq, nullptr, qkv, DIN, QKVLD, 0);
    gemm_xwT_kernel<<<gp, blk>>>(x, Wk, nullptr, qkv, DIN, QKVLD, DOUT);
    gemm_xwT_kernel<<<gp, blk>>>(x, Wv, nullptr, qkv, DIN, QKVLD, 2 * DOUT);

    // Causal flash attention
    attn_kernel<<<dim3(SEQ / 64, BB * NH), blk, ATTN_SMEM>>>(qkv, ctx);

    // Output projection + bias
    gemm_xwT_kernel<<<gp, blk>>>(ctx, Wo, bo, out, DOUT, DOUT, 0);
}